// round 8
// baseline (speedup 1.0000x reference)
#include <cuda_runtime.h>
#include <stdint.h>

// Gemma4VisionPooler: 2x2 mean-pool over a 64x64 patch grid, scaled by sqrt(H).
#define BB      16
#define LL      4096
#define HH      1152
#define OUT_LEN 1024
#define KP      2
#define KSQ     4

// scale = sqrt(1152) / 4  (fold mean 1/k^2 and *sqrt(hidden) into one multiply)
#define POOL_SCALE 8.48528137423857f

// Scratch (no allocations allowed).
__device__ int g_map[BB * OUT_LEN * KSQ];   // source patch index per (b, seg, slot), -1 if empty
__device__ int g_maxx[BB];                  // max(clamped x) + 1 per batch
__device__ int g_pos32;                     // 1 if pixel_position_ids is int32, 0 if int64

// ---------------------------------------------------------------------------
// Kernel A: detect position dtype. If the buffer is int32 (x,y) pairs, an
// int64-interpreted slot for a patch with y>0 holds x + (y<<32) >= 2^32.
// Genuine int64 grid positions are tiny. Scan 8192 slots (covers y up to 63
// in the int32 interpretation).
// ---------------------------------------------------------------------------
__global__ void detect_kernel(const long long* __restrict__ posraw) {
    const int t = threadIdx.x;
    int bad = 0;
    for (int i = t; i < 8192; i += blockDim.x) {
        long long v = posraw[i];
        if (v < 0 || v >= (1LL << 32)) bad = 1;
    }
    __syncthreads();
    if (t == 0) g_pos32 = 0;
    __syncthreads();
    if (bad) g_pos32 = 1;   // benign race: all writers store 1
}

// Dtype-dispatched position load.
__device__ __forceinline__ void load_xy(const void* pos, long long idx,
                                        long long& x, long long& y) {
    if (g_pos32) {
        const int* p = (const int*)pos;
        x = p[2 * idx];
        y = p[2 * idx + 1];
    } else {
        const long long* p = (const long long*)pos;
        x = p[2 * idx];
        y = p[2 * idx + 1];
    }
}

// ---------------------------------------------------------------------------
// Kernel 0: init map to -1, reduce max_x per batch.
// ---------------------------------------------------------------------------
__global__ void prep_kernel(const void* __restrict__ pos) {
    const int b = blockIdx.x;
    const int t = threadIdx.x;

    int* mp = g_map + b * OUT_LEN * KSQ;
    for (int i = t; i < OUT_LEN * KSQ; i += blockDim.x) mp[i] = -1;

    int mx = 0;
    for (int i = t; i < LL; i += blockDim.x) {
        long long x, y;
        load_xy(pos, (long long)b * LL + i, x, y);
        if (x < 0) x = 0;
        mx = max(mx, (int)x);
    }
    __shared__ int smax[32];
    #pragma unroll
    for (int o = 16; o; o >>= 1) mx = max(mx, __shfl_xor_sync(0xffffffffu, mx, o));
    if ((t & 31) == 0) smax[t >> 5] = mx;
    __syncthreads();
    if (t < 32) {
        int nwarps = blockDim.x >> 5;
        int v = (t < nwarps) ? smax[t] : 0;
        #pragma unroll
        for (int o = 16; o; o >>= 1) v = max(v, __shfl_xor_sync(0xffffffffu, v, o));
        if (t == 0) g_maxx[b] = v + 1;
    }
}

// ---------------------------------------------------------------------------
// Kernel 1: build inverse map. Deterministic slot = (x%k) + k*(y%k), so the
// 4-way sum order in the pool kernel is fixed (deterministic output).
// ---------------------------------------------------------------------------
__global__ void build_map_kernel(const void* __restrict__ pos) {
    int idx = blockIdx.x * blockDim.x + threadIdx.x;   // over BB*LL
    if (idx >= BB * LL) return;
    int b = idx / LL;
    int l = idx - b * LL;
    long long x, y;
    load_xy(pos, idx, x, y);
    if (x < 0) x = 0;
    if (y < 0) y = 0;
    int xi = (int)x, yi = (int)y;
    int segw = g_maxx[b] / KP;
    int seg  = (xi / KP) + segw * (yi / KP);
    int slot = (xi % KP) + KP * (yi % KP);
    if (seg >= 0 && seg < OUT_LEN)
        g_map[(b * OUT_LEN + seg) * KSQ + slot] = l;
}

// ---------------------------------------------------------------------------
// Kernel 2: gather-pool. One block per (b, seg); 288 threads = 1152/4 float4
// lanes. 4 coalesced float4 loads + 1 float4 store per thread. Padded source
// patches contribute zero, matching the reference's zero-before-pool
// semantics (sum always divided by k^2).
// ---------------------------------------------------------------------------
__global__ void __launch_bounds__(288) pool_kernel(
    const float* __restrict__ hs,
    const uint8_t* __restrict__ pad,
    float* __restrict__ out,
    int mask_elems)
{
    const int bs = blockIdx.x;            // b*OUT_LEN + seg
    const int b  = bs >> 10;              // / OUT_LEN
    const int t  = threadIdx.x;

    const int* mp = g_map + bs * KSQ;
    const int l0 = mp[0], l1 = mp[1], l2 = mp[2], l3 = mp[3];

    const long long base = (long long)b * LL;
    const float w0 = (l0 >= 0 && !pad[base + l0]) ? 1.0f : 0.0f;
    const float w1 = (l1 >= 0 && !pad[base + l1]) ? 1.0f : 0.0f;
    const float w2 = (l2 >= 0 && !pad[base + l2]) ? 1.0f : 0.0f;
    const float w3 = (l3 >= 0 && !pad[base + l3]) ? 1.0f : 0.0f;

    const int s0 = l0 >= 0 ? l0 : 0;
    const int s1 = l1 >= 0 ? l1 : 0;
    const int s2 = l2 >= 0 ? l2 : 0;
    const int s3 = l3 >= 0 ? l3 : 0;

    const float4* r0 = (const float4*)(hs + (base + s0) * HH);
    const float4* r1 = (const float4*)(hs + (base + s1) * HH);
    const float4* r2 = (const float4*)(hs + (base + s2) * HH);
    const float4* r3 = (const float4*)(hs + (base + s3) * HH);

    float4 v0 = r0[t];
    float4 v1 = r1[t];
    float4 v2 = r2[t];
    float4 v3 = r3[t];

    float4 acc;
    acc.x = (v0.x * w0 + v1.x * w1 + v2.x * w2 + v3.x * w3) * POOL_SCALE;
    acc.y = (v0.y * w0 + v1.y * w1 + v2.y * w2 + v3.y * w3) * POOL_SCALE;
    acc.z = (v0.z * w0 + v1.z * w1 + v2.z * w2 + v3.z * w3) * POOL_SCALE;
    acc.w = (v0.w * w0 + v1.w * w1 + v2.w * w2 + v3.w * w3) * POOL_SCALE;

    ((float4*)(out + (long long)bs * HH))[t] = acc;

    // optional mask region (pooled padding_positions = counts > 0) as float
    if (t == 0 && bs < mask_elems) {
        float m = (l0 >= 0 || l1 >= 0 || l2 >= 0 || l3 >= 0) ? 1.0f : 0.0f;
        out[(long long)BB * OUT_LEN * HH + bs] = m;
    }
}

// ---------------------------------------------------------------------------
extern "C" void kernel_launch(void* const* d_in, const int* in_sizes, int n_in,
                              void* d_out, int out_size) {
    const float*   hs  = (const float*)d_in[0];   // [B, L, H] f32
    const void*    pos = d_in[1];                 // [B, L, 2] i32 or i64 (detected)
    const uint8_t* pad = (const uint8_t*)d_in[2]; // [B, L] bool
    // d_in[3] = output_length (constant 1024, baked in)

    float* out = (float*)d_out;

    const long long hs_elems = (long long)BB * OUT_LEN * HH;
    int mask_elems = 0;
    if ((long long)out_size > hs_elems) {
        long long extra = (long long)out_size - hs_elems;
        mask_elems = (int)(extra < (long long)(BB * OUT_LEN) ? extra
                                                             : (long long)(BB * OUT_LEN));
    }

    detect_kernel<<<1, 256>>>((const long long*)pos);
    prep_kernel<<<BB, 256>>>(pos);
    build_map_kernel<<<(BB * LL + 255) / 256, 256>>>(pos);
    pool_kernel<<<BB * OUT_LEN, 288>>>(hs, pad, out, mask_elems);
}

// round 10
// speedup vs baseline: 1.0947x; 1.0947x over previous
#include <cuda_runtime.h>
#include <stdint.h>

// Gemma4VisionPooler: 2x2 mean-pool over a 64x64 patch grid, scaled by sqrt(H).
#define BB      16
#define LL      4096
#define HH      1152
#define OUT_LEN 1024
#define KP      2
#define KSQ     4

// scale = sqrt(1152) / 4  (fold mean 1/k^2 and *sqrt(hidden) into one multiply)
#define POOL_SCALE 8.48528137423857f

// Scratch (no allocations allowed).
__device__ int g_map[BB * OUT_LEN * KSQ];   // source patch index per (b, seg, slot), -1 if empty

// ---------------------------------------------------------------------------
// Fused prep: one block per batch.
//   Pass 0: init this batch's map slots to -1.
//   Pass 1: dtype-detect on this batch's slot range. Interpreted as int64,
//           an int32 (x,y) pair with y>0 reads as x + (y<<32) >= 2^32; every
//           batch holds a full grid (y up to 63), so detection is guaranteed
//           per-block. Genuine int64 positions read as 0..63 -> no trigger.
//           Slot range [b*LL, b*LL+LL) is in bounds under BOTH dtypes.
//   Pass 2: block-reduce max(clamped x) with the detected dtype.
//   Pass 3: build inverse map with deterministic slot = (x%k) + k*(y%k),
//           fixing the 4-way sum order in the pool kernel.
// All three data passes touch the same 64KB -> L1/L2 resident after pass 1.
// ---------------------------------------------------------------------------
__global__ void __launch_bounds__(256) prep_all_kernel(const void* __restrict__ pos) {
    const int b = blockIdx.x;
    const int t = threadIdx.x;

    int* mp = g_map + b * OUT_LEN * KSQ;
    #pragma unroll
    for (int i = t; i < OUT_LEN * KSQ; i += 256) mp[i] = -1;

    // --- Pass 1: dtype detection (block-local) ---
    __shared__ int s_pos32;
    if (t == 0) s_pos32 = 0;
    __syncthreads();
    {
        const long long* praw = (const long long*)pos + (long long)b * LL;
        int bad = 0;
        #pragma unroll
        for (int i = t; i < LL; i += 256) {
            long long v = praw[i];
            if (v < 0 || v >= (1LL << 32)) bad = 1;
        }
        if (bad) s_pos32 = 1;   // benign race: all writers store 1
    }
    __syncthreads();
    const int pos32 = s_pos32;

    const int*       p32 = (const int*)pos + (long long)b * LL * 2;
    const long long* p64 = (const long long*)pos + (long long)b * LL * 2;

    // --- Pass 2: max over clamped x ---
    int mx = 0;
    #pragma unroll
    for (int i = t; i < LL; i += 256) {
        long long x = pos32 ? (long long)p32[2 * i] : p64[2 * i];
        if (x < 0) x = 0;
        mx = max(mx, (int)x);
    }
    __shared__ int smax[8];
    #pragma unroll
    for (int o = 16; o; o >>= 1) mx = max(mx, __shfl_xor_sync(0xffffffffu, mx, o));
    if ((t & 31) == 0) smax[t >> 5] = mx;
    __syncthreads();
    __shared__ int s_segw;
    if (t == 0) {
        int v = smax[0];
        #pragma unroll
        for (int w = 1; w < 8; w++) v = max(v, smax[w]);
        s_segw = (v + 1) / KP;
    }
    __syncthreads();
    const int segw = s_segw;

    // --- Pass 3: build inverse map for this batch ---
    #pragma unroll
    for (int l = t; l < LL; l += 256) {
        long long x, y;
        if (pos32) { x = p32[2 * l]; y = p32[2 * l + 1]; }
        else       { x = p64[2 * l]; y = p64[2 * l + 1]; }
        if (x < 0) x = 0;
        if (y < 0) y = 0;
        int xi = (int)x, yi = (int)y;
        int seg  = (xi / KP) + segw * (yi / KP);
        int slot = (xi % KP) + KP * (yi % KP);
        if (seg >= 0 && seg < OUT_LEN)
            mp[seg * KSQ + slot] = l;
    }
}

// ---------------------------------------------------------------------------
// Gather-pool. One block per (b, seg); 288 threads = 1152/4 float4 lanes.
// 4 coalesced float4 loads + 1 float4 store per thread. Padded source
// patches contribute zero (weight multiply), matching the reference's
// zero-before-pool semantics (sum always divided by k^2).
// ---------------------------------------------------------------------------
__global__ void __launch_bounds__(288) pool_kernel(
    const float* __restrict__ hs,
    const uint8_t* __restrict__ pad,
    float* __restrict__ out,
    int mask_elems)
{
    const int bs = blockIdx.x;            // b*OUT_LEN + seg
    const int b  = bs >> 10;              // / OUT_LEN
    const int t  = threadIdx.x;

    const int* mp = g_map + bs * KSQ;
    const int l0 = mp[0], l1 = mp[1], l2 = mp[2], l3 = mp[3];

    const long long base = (long long)b * LL;
    const float w0 = (l0 >= 0 && !pad[base + (l0 >= 0 ? l0 : 0)]) ? 1.0f : 0.0f;
    const float w1 = (l1 >= 0 && !pad[base + (l1 >= 0 ? l1 : 0)]) ? 1.0f : 0.0f;
    const float w2 = (l2 >= 0 && !pad[base + (l2 >= 0 ? l2 : 0)]) ? 1.0f : 0.0f;
    const float w3 = (l3 >= 0 && !pad[base + (l3 >= 0 ? l3 : 0)]) ? 1.0f : 0.0f;

    const int s0 = l0 >= 0 ? l0 : 0;
    const int s1 = l1 >= 0 ? l1 : 0;
    const int s2 = l2 >= 0 ? l2 : 0;
    const int s3 = l3 >= 0 ? l3 : 0;

    const float4* r0 = (const float4*)(hs + (base + s0) * HH);
    const float4* r1 = (const float4*)(hs + (base + s1) * HH);
    const float4* r2 = (const float4*)(hs + (base + s2) * HH);
    const float4* r3 = (const float4*)(hs + (base + s3) * HH);

    float4 v0 = r0[t];
    float4 v1 = r1[t];
    float4 v2 = r2[t];
    float4 v3 = r3[t];

    float4 acc;
    acc.x = (v0.x * w0 + v1.x * w1 + v2.x * w2 + v3.x * w3) * POOL_SCALE;
    acc.y = (v0.y * w0 + v1.y * w1 + v2.y * w2 + v3.y * w3) * POOL_SCALE;
    acc.z = (v0.z * w0 + v1.z * w1 + v2.z * w2 + v3.z * w3) * POOL_SCALE;
    acc.w = (v0.w * w0 + v1.w * w1 + v2.w * w2 + v3.w * w3) * POOL_SCALE;

    ((float4*)(out + (long long)bs * HH))[t] = acc;

    // optional mask region (pooled padding_positions = counts > 0) as float
    if (t == 0 && bs < mask_elems) {
        float m = (l0 >= 0 || l1 >= 0 || l2 >= 0 || l3 >= 0) ? 1.0f : 0.0f;
        out[(long long)BB * OUT_LEN * HH + bs] = m;
    }
}

// ---------------------------------------------------------------------------
extern "C" void kernel_launch(void* const* d_in, const int* in_sizes, int n_in,
                              void* d_out, int out_size) {
    const float*   hs  = (const float*)d_in[0];   // [B, L, H] f32
    const void*    pos = d_in[1];                 // [B, L, 2] i32 or i64 (detected)
    const uint8_t* pad = (const uint8_t*)d_in[2]; // [B, L] bool
    // d_in[3] = output_length (constant 1024, baked in)

    float* out = (float*)d_out;

    const long long hs_elems = (long long)BB * OUT_LEN * HH;
    int mask_elems = 0;
    if ((long long)out_size > hs_elems) {
        long long extra = (long long)out_size - hs_elems;
        mask_elems = (int)(extra < (long long)(BB * OUT_LEN) ? extra
                                                             : (long long)(BB * OUT_LEN));
    }

    prep_all_kernel<<<BB, 256>>>(pos);
    pool_kernel<<<BB * OUT_LEN, 288>>>(hs, pad, out, mask_elems);
}